// round 17
// baseline (speedup 1.0000x reference)
#include <cuda_runtime.h>
#include <cuda_fp16.h>
#include <cstdint>

#define NODE_DIM 128
#define EDGE_DIM 64
#define K1       192
#define N_OUT    128
#define NWARPS   16
#define THREADS  (NWARPS * 32)    // 512
#define CTA_M    256              // 8 row-groups x 32 rows, 2 n-halves
#define W1_LD    200   // fp16 elems; 400B stride = 16 mod 128 -> conflict-free
#define W2_LD    136   // 272B stride = 16 mod 128
#define XS_LD    200   // x-stage stride (192 data + pad)
#define HS_LD    136   // h-stage stride (128 data + pad)
#define LN_EPS   1e-5f

// ---- smem layout (bytes) ----
#define SM_W1H  0
#define SM_W2H  (SM_W1H + 128 * W1_LD * 2)     // 51200
#define SM_XS   (SM_W2H + 128 * W2_LD * 2)     // 86016 (x-stage 256*400=102400; h-stage overlays)
#define SM_PART (SM_XS + 256 * XS_LD * 2)      // 188416 (256 rows * 2 nh * float2)
#define SM_VEC  (SM_PART + 256 * 2 * 8)        // 192512
#define SMEM_BYTES (SM_VEC + 4 * 128 * 4)      // 194560

__device__ __forceinline__ uint32_t smem_u32(const void* p) {
    uint32_t a;
    asm("{ .reg .u64 t; cvta.to.shared.u64 t, %1; cvt.u32.u64 %0, t; }" : "=r"(a) : "l"(p));
    return a;
}

__device__ __forceinline__ void mma16816(float* d, const uint32_t* a, uint32_t b0, uint32_t b1) {
    asm volatile(
        "mma.sync.aligned.m16n8k16.row.col.f32.f16.f16.f32 "
        "{%0,%1,%2,%3},{%4,%5,%6,%7},{%8,%9},{%0,%1,%2,%3};"
        : "+f"(d[0]), "+f"(d[1]), "+f"(d[2]), "+f"(d[3])
        : "r"(a[0]), "r"(a[1]), "r"(a[2]), "r"(a[3]), "r"(b0), "r"(b1));
}

__device__ __forceinline__ void ldsm_x2(uint32_t& r0, uint32_t& r1, uint32_t addr) {
    asm volatile("ldmatrix.sync.aligned.m8n8.x2.shared.b16 {%0,%1}, [%2];"
                 : "=r"(r0), "=r"(r1) : "r"(addr));
}

__device__ __forceinline__ void ldsm_x4(uint32_t& r0, uint32_t& r1, uint32_t& r2, uint32_t& r3,
                                        uint32_t addr) {
    asm volatile("ldmatrix.sync.aligned.m8n8.x4.shared.b16 {%0,%1,%2,%3}, [%4];"
                 : "=r"(r0), "=r"(r1), "=r"(r2), "=r"(r3) : "r"(addr));
}

__device__ __forceinline__ uint32_t pack_h2(float x, float y) {
    __half2 h = __floats2half2_rn(x, y);
    return reinterpret_cast<uint32_t&>(h);
}

__device__ __forceinline__ float silu_f(float x) {
    return __fdividef(x, 1.0f + __expf(-x));
}

__global__ __launch_bounds__(THREADS, 1)
void edge_mlp_kernel(const float* __restrict__ src, const float* __restrict__ edge,
                     const float* __restrict__ W1, const float* __restrict__ b1v,
                     const float* __restrict__ gammav, const float* __restrict__ betav,
                     const float* __restrict__ W2, const float* __restrict__ b2v,
                     float* __restrict__ out, int E, int num_tiles)
{
    extern __shared__ char smem[];
    __half* w1h = reinterpret_cast<__half*>(smem + SM_W1H);
    __half* w2h = reinterpret_cast<__half*>(smem + SM_W2H);
    float* s_b1 = reinterpret_cast<float*>(smem + SM_VEC);
    float* s_b2 = s_b1 + 128;
    float* s_g  = s_b1 + 256;
    float* s_bt = s_b1 + 384;
    float2* s_part = reinterpret_cast<float2*>(smem + SM_PART);   // [row][nh]

    const int tid  = threadIdx.x;
    const int lane = tid & 31;
    const int wid  = tid >> 5;
    const int g    = lane >> 2;   // 0..7
    const int t    = lane & 3;    // 0..3
    const int mg   = wid >> 1;    // row-group 0..7
    const int nh   = wid & 1;     // n-half
    const int ml   = mg * 32;     // local row base

    const uint32_t sb = smem_u32(smem);

    // ---- one-time weight conversion (fp16, transposed, padded) ----
    for (int i = tid; i < 128 * K1; i += THREADS) {
        int n = i / K1, k = i - n * K1;
        w1h[n * W1_LD + k] = __float2half_rn(W1[k * N_OUT + n]);
    }
    for (int i = tid; i < 128 * 128; i += THREADS) {
        int n = i >> 7, k = i & 127;
        w2h[n * W2_LD + k] = __float2half_rn(W2[k * N_OUT + n]);
    }
    if (tid < 128) {
        s_b1[tid] = b1v[tid];
        s_b2[tid] = b2v[tid];
        s_g[tid]  = gammav[tid];
        s_bt[tid] = betav[tid];
    }

    // ---- per-lane ldmatrix addresses ----
    const int lrow  = lane & 7;
    const int lhalf = (lane >> 3) & 1;
    // B bases (x2): rows nh*64 + 8j + lrow
    const uint32_t w1b = sb + SM_W1H + (uint32_t)((nh * 64 + lrow) * (W1_LD * 2) + lhalf * 16);
    const uint32_t w2b = sb + SM_W2H + (uint32_t)((nh * 64 + lrow) * (W2_LD * 2) + lhalf * 16);
    // A bases (x4): rows ml + mf*16 + (lane&15), k-col (lane>>4)*16 bytes
    const int arow = ml + (lane & 15);
    const uint32_t xsA = sb + SM_XS + (uint32_t)(arow * (XS_LD * 2) + (lane >> 4) * 16);
    const uint32_t hsA = sb + SM_XS + (uint32_t)(arow * (HS_LD * 2) + (lane >> 4) * 16);

    // x staging map: c = tid&7 (16B chunk), base row = tid>>3 (64 rows/pass)
    const int xc = tid & 7;
    const int xr = tid >> 3;

    for (int tile = blockIdx.x; tile < num_tiles; tile += gridDim.x) {
        __syncthreads();   // protect x/h region from previous tile's readers

        // ================= Stage x (coalesced LDG.128 -> fp16 STS) =================
        {
            const int rglob0 = tile * CTA_M;
            #pragma unroll
            for (int p4 = 0; p4 < 4; ++p4) {
                const int rl = p4 * 64 + xr;
                const int rg = rglob0 + rl;
                const bool vr = rg < E;
                const float* srow = src  + (size_t)(vr ? rg : 0) * NODE_DIM;
                const float* erow = edge + (size_t)(vr ? rg : 0) * EDGE_DIM;
                uint32_t sdst = sb + SM_XS + (uint32_t)(rl * (XS_LD * 2));
                #pragma unroll
                for (int p = 0; p < 6; ++p) {
                    const int f = p * 32 + xc * 4;
                    float4 v = make_float4(0.f, 0.f, 0.f, 0.f);
                    if (vr) v = (p < 4) ? *(const float4*)(srow + f)
                                        : *(const float4*)(erow + (f - 128));
                    uint32_t h01 = pack_h2(v.x, v.y);
                    uint32_t h23 = pack_h2(v.z, v.w);
                    asm volatile("st.shared.v2.b32 [%0], {%1, %2};"
                                 :: "r"(sdst + (uint32_t)(f * 2)), "r"(h01), "r"(h23));
                }
            }
        }
        __syncthreads();

        // ================= GEMM1: C1[2mf][8j][4] = x @ W1 (n-half) =================
        float C1[2][8][4];
        #pragma unroll
        for (int mf = 0; mf < 2; ++mf)
            #pragma unroll
            for (int j = 0; j < 8; ++j)
                #pragma unroll
                for (int q = 0; q < 4; ++q) C1[mf][j][q] = 0.f;

        #pragma unroll 1
        for (int s = 0; s < 12; ++s) {
            uint32_t a0[4], a1[4];
            ldsm_x4(a0[0], a0[1], a0[2], a0[3], xsA + (uint32_t)(s * 32));
            ldsm_x4(a1[0], a1[1], a1[2], a1[3], xsA + (uint32_t)(16 * (XS_LD * 2) + s * 32));
            #pragma unroll
            for (int j = 0; j < 8; ++j) {
                uint32_t b0, b1;
                ldsm_x2(b0, b1, w1b + (uint32_t)(j * (8 * W1_LD * 2) + s * 32));
                mma16816(C1[0][j], a0, b0, b1);
                mma16816(C1[1][j], a1, b0, b1);
            }
        }

        // ============ Epilogue 1: +b1, cross-warp LN partials ============
        // slot (mf,h): local row = ml + mf*16 + h*8 + g
        #pragma unroll
        for (int mf = 0; mf < 2; ++mf) {
            #pragma unroll
            for (int h = 0; h < 2; ++h) {
                float sum = 0.f, ssq = 0.f;
                #pragma unroll
                for (int j = 0; j < 8; ++j) {
                    const int col = nh * 64 + 8 * j + 2 * t;
                    float x0 = C1[mf][j][2 * h + 0] + s_b1[col];
                    float x1 = C1[mf][j][2 * h + 1] + s_b1[col + 1];
                    C1[mf][j][2 * h + 0] = x0;
                    C1[mf][j][2 * h + 1] = x1;
                    sum += x0 + x1;
                    ssq = fmaf(x0, x0, ssq);
                    ssq = fmaf(x1, x1, ssq);
                }
                sum += __shfl_xor_sync(0xffffffffu, sum, 1);
                sum += __shfl_xor_sync(0xffffffffu, sum, 2);
                ssq += __shfl_xor_sync(0xffffffffu, ssq, 1);
                ssq += __shfl_xor_sync(0xffffffffu, ssq, 2);
                if (t == 0) {
                    const int rl = ml + mf * 16 + h * 8 + g;
                    s_part[rl * 2 + nh] = make_float2(sum, ssq);
                }
            }
        }
        __syncthreads();

        // ============ LN apply + SiLU + pack + STS h (overlays x-stage) ============
        #pragma unroll
        for (int mf = 0; mf < 2; ++mf) {
            #pragma unroll
            for (int h = 0; h < 2; ++h) {
                const int rl = ml + mf * 16 + h * 8 + g;
                float2 pa = s_part[rl * 2 + 0];
                float2 pb = s_part[rl * 2 + 1];
                float mu  = (pa.x + pb.x) * (1.f / 128.f);
                float var = (pa.y + pb.y) * (1.f / 128.f) - mu * mu;
                float rs  = rsqrtf(fmaxf(var, 0.f) + LN_EPS);
                const uint32_t hrow = sb + SM_XS + (uint32_t)(rl * (HS_LD * 2));
                #pragma unroll
                for (int j = 0; j < 8; ++j) {
                    const int col = nh * 64 + 8 * j + 2 * t;
                    float y0 = (C1[mf][j][2 * h + 0] - mu) * rs * s_g[col]     + s_bt[col];
                    float y1 = (C1[mf][j][2 * h + 1] - mu) * rs * s_g[col + 1] + s_bt[col + 1];
                    uint32_t p = pack_h2(silu_f(y0), silu_f(y1));
                    asm volatile("st.shared.b32 [%0], %1;"
                                 :: "r"(hrow + (uint32_t)(col * 2)), "r"(p));
                }
            }
        }
        __syncthreads();

        // ================= GEMM2: C2 = h @ W2 (n-half) =================
        float C2[2][8][4];
        #pragma unroll
        for (int mf = 0; mf < 2; ++mf)
            #pragma unroll
            for (int j = 0; j < 8; ++j)
                #pragma unroll
                for (int q = 0; q < 4; ++q) C2[mf][j][q] = 0.f;

        #pragma unroll 1
        for (int s = 0; s < 8; ++s) {
            uint32_t a0[4], a1[4];
            ldsm_x4(a0[0], a0[1], a0[2], a0[3], hsA + (uint32_t)(s * 32));
            ldsm_x4(a1[0], a1[1], a1[2], a1[3], hsA + (uint32_t)(16 * (HS_LD * 2) + s * 32));
            #pragma unroll
            for (int j = 0; j < 8; ++j) {
                uint32_t b0, b1;
                ldsm_x2(b0, b1, w2b + (uint32_t)(j * (8 * W2_LD * 2) + s * 32));
                mma16816(C2[0][j], a0, b0, b1);
                mma16816(C2[1][j], a1, b0, b1);
            }
        }

        // ============ Epilogue 2: +b2, SiLU, store ============
        const int rglob = tile * CTA_M + ml;
        #pragma unroll
        for (int mf = 0; mf < 2; ++mf) {
            #pragma unroll
            for (int h = 0; h < 2; ++h) {
                const int row = rglob + mf * 16 + h * 8 + g;
                if (row < E) {
                    float* op = out + (size_t)row * N_OUT;
                    #pragma unroll
                    for (int j = 0; j < 8; ++j) {
                        const int col = nh * 64 + 8 * j + 2 * t;
                        *(float2*)(op + col) =
                            make_float2(silu_f(C2[mf][j][2 * h + 0] + s_b2[col]),
                                        silu_f(C2[mf][j][2 * h + 1] + s_b2[col + 1]));
                    }
                }
            }
        }
    }
}

extern "C" void kernel_launch(void* const* d_in, const int* in_sizes, int n_in,
                              void* d_out, int out_size) {
    const float* src   = (const float*)d_in[0];
    const float* edge  = (const float*)d_in[1];
    const float* W1    = (const float*)d_in[2];
    const float* b1    = (const float*)d_in[3];
    const float* gamma = (const float*)d_in[4];
    const float* beta  = (const float*)d_in[5];
    const float* W2    = (const float*)d_in[6];
    const float* b2    = (const float*)d_in[7];
    float* out = (float*)d_out;

    int E = in_sizes[0] / NODE_DIM;
    int num_tiles = (E + CTA_M - 1) / CTA_M;

    static int smem_set = 0;
    if (!smem_set) {
        cudaFuncSetAttribute(edge_mlp_kernel, cudaFuncAttributeMaxDynamicSharedMemorySize, SMEM_BYTES);
        smem_set = 1;
    }
    int grid = num_tiles < 152 ? num_tiles : 152;
    edge_mlp_kernel<<<grid, THREADS, SMEM_BYTES>>>(src, edge, W1, b1, gamma, beta, W2, b2,
                                                   out, E, num_tiles);
}